// round 4
// baseline (speedup 1.0000x reference)
#include <cuda_runtime.h>
#include <cstdint>

#define NB_CAT  8192
#define RANK    16
#define N_COLS  4

// out[p] = sum_c dot(cf[c, x[p,c], :16], cf[c, y[p,c], :16]) + (x[p,c]==y[p,c] ? std[c,x]^2 : 0)
//
// R4 layout: 8 lanes per pair (sub = lane&7 = float2 chunk of the 16-float
// row), 4 pairs per warp-iter (unit = lane>>3). Columns iterated in-register.
//
// Rationale: R3's LDG.128 packed 8 distinct lines per instruction; within-LDG
// wavefront replays cost ~2.07 cyc/wf vs ~1.0 cross-LDG (B300 measured).
// Splitting each row across 8 lanes x float2 halves lines-per-LDG to 4,
// trading cheap LSU issue slots (2M LDGs, well under the 1/cyc/SM floor)
// for cheaper wavefronts. Total wavefronts unchanged: 1 wf per 64B row.

__global__ __launch_bounds__(256, 8) void pair_cov_kernel(
    const int*   __restrict__ x,
    const int*   __restrict__ y,
    const float* __restrict__ cf,     // [N_COLS, NB_CAT, RANK]
    const float* __restrict__ stdv,   // [N_COLS, NB_CAT]
    float*       __restrict__ out,
    int n_pairs)
{
    const int lane = threadIdx.x & 31;
    const int sub  = lane & 7;        // float2 chunk within a row (0..7)
    const int unit = lane >> 3;       // pair slot within warp-iter (0..3)

    const int warp_global = (int)((blockIdx.x * blockDim.x + threadIdx.x) >> 5);
    const int nwarps      = (int)((gridDim.x * blockDim.x) >> 5);

    const float2* cf2 = (const float2*)cf;   // row r -> cf2[r*8 + sub]

    for (int base = warp_global * 4; base < n_pairs; base += nwarps * 4) {
        const int p = base + unit;   // base multiple of 4, n_pairs multiple of 4

        // Per-pair index vectors: 4 distinct int4 = 64B = 1 wf (broadcast to 8 lanes)
        const int4 xi = __ldcg((const int4*)x + p);
        const int4 yi = __ldcg((const int4*)y + p);

        float acc = 0.0f;

        #pragma unroll
        for (int c = 0; c < N_COLS; c++) {
            const int xc = (c == 0) ? xi.x : (c == 1) ? xi.y : (c == 2) ? xi.z : xi.w;
            const int yc = (c == 0) ? yi.x : (c == 1) ? yi.y : (c == 2) ? yi.z : yi.w;

            // 8 lanes x float2 = one 64B row; 4 rows (4 lines) per LDG.64
            const float2 a = cf2[(size_t)(c * NB_CAT + xc) * (RANK / 2) + sub];
            const float2 b = cf2[(size_t)(c * NB_CAT + yc) * (RANK / 2) + sub];

            acc += a.x * b.x;
            acc += a.y * b.y;
        }

        // Diagonal term: lanes sub=0..3 of each pair group own column `sub`
        if (sub < N_COLS) {
            const int xd = (sub == 0) ? xi.x : (sub == 1) ? xi.y : (sub == 2) ? xi.z : xi.w;
            const int yd = (sub == 0) ? yi.x : (sub == 1) ? yi.y : (sub == 2) ? yi.z : yi.w;
            if (xd == yd) {
                const float s = stdv[sub * NB_CAT + xd];
                acc += s * s;
            }
        }

        // Reduce over the 8 chunk lanes of each pair group
        acc += __shfl_xor_sync(0xffffffffu, acc, 1);
        acc += __shfl_xor_sync(0xffffffffu, acc, 2);
        acc += __shfl_xor_sync(0xffffffffu, acc, 4);

        if (sub == 0) {
            out[p] = acc;   // lanes 0,8,16,24 -> 4 consecutive floats -> 1 wf
        }
    }
}

extern "C" void kernel_launch(void* const* d_in, const int* in_sizes, int n_in,
                              void* d_out, int out_size)
{
    const int*   x    = (const int*)d_in[0];
    const int*   y    = (const int*)d_in[1];
    const float* cf   = (const float*)d_in[2];
    const float* stdv = (const float*)d_in[3];
    float*       out  = (float*)d_out;

    const int n_pairs = out_size;  // 1048576

    // Single resident wave: 148 SMs x 8 blocks (launch_bounds guarantees 8/SM)
    const int threads = 256;
    const int blocks  = 148 * 8;
    pair_cov_kernel<<<blocks, threads>>>(x, y, cf, stdv, out, n_pairs);
}

// round 5
// speedup vs baseline: 1.1745x; 1.1745x over previous
#include <cuda_runtime.h>
#include <cuda_fp16.h>
#include <cstdint>

#define NB_CAT  8192
#define RANK    16
#define N_COLS  4

// R5: covar_factor is converted to fp16 in a static device buffer each launch.
// This halves the L2 sector traffic per gathered row (32B vs 64B) and doubles
// the L1-resident fraction of the table (1MB vs 2MB) — R3/R4 profiling showed
// the kernel is bound by the full-chip LTS (L2) throughput cap (~456MB of
// L2->L1 fill traffic at ~11.5TB/s). std stays fp32 (diagonal term exact).

__device__ __half2 g_cfh[N_COLS * NB_CAT * RANK / 2];   // 4 MB, same layout as cf

__global__ __launch_bounds__(256) void convert_cf_kernel(const float* __restrict__ cf)
{
    const int i = blockIdx.x * blockDim.x + threadIdx.x;   // half2 index
    const int n = N_COLS * NB_CAT * RANK / 2;              // 1,048,576
    if (i < n) {
        const float2 v = ((const float2*)cf)[i];
        g_cfh[i] = __float22half2_rn(v);
    }
}

// out[p] = sum_c dot(cf[c,x[p,c],:16], cf[c,y[p,c],:16]) + (x==y ? std^2 : 0)
// Layout (same as R3): 4 lanes per pair (sub = 8-byte chunk of the 32B fp16
// row), 8 pairs per warp-iter, columns iterated in-register, fp32 accumulate.

__global__ __launch_bounds__(256, 8) void pair_cov_kernel(
    const int*   __restrict__ x,
    const int*   __restrict__ y,
    const float* __restrict__ stdv,   // [N_COLS, NB_CAT]
    float*       __restrict__ out,
    int n_pairs)
{
    const int lane = threadIdx.x & 31;
    const int sub  = lane & 3;        // 8B chunk within the 32B fp16 row
    const int unit = lane >> 2;       // pair slot within warp-iter (0..7)

    const int warp_global = (int)((blockIdx.x * blockDim.x + threadIdx.x) >> 5);
    const int nwarps      = (int)((gridDim.x * blockDim.x) >> 5);

    // row r occupies 8 half2 (32B); lane sub takes half2 slots {2*sub, 2*sub+1}
    const __half2* cfh = g_cfh;

    for (int base = warp_global * 8; base < n_pairs; base += nwarps * 8) {
        const int p = base + unit;   // base multiple of 8, n_pairs multiple of 8

        const int4 xi = __ldcg((const int4*)x + p);
        const int4 yi = __ldcg((const int4*)y + p);

        float acc = 0.0f;

        #pragma unroll
        for (int c = 0; c < N_COLS; c++) {
            const int xc = (c == 0) ? xi.x : (c == 1) ? xi.y : (c == 2) ? xi.z : xi.w;
            const int yc = (c == 0) ? yi.x : (c == 1) ? yi.y : (c == 2) ? yi.z : yi.w;

            // 4 lanes x 8B = one 32B fp16 row = one L1 wavefront, one L2 sector
            const uint2 av = *(const uint2*)(cfh + (size_t)(c * NB_CAT + xc) * 8 + sub * 2);
            const uint2 bv = *(const uint2*)(cfh + (size_t)(c * NB_CAT + yc) * 8 + sub * 2);

            const float2 a0 = __half22float2(*(const __half2*)&av.x);
            const float2 a1 = __half22float2(*(const __half2*)&av.y);
            const float2 b0 = __half22float2(*(const __half2*)&bv.x);
            const float2 b1 = __half22float2(*(const __half2*)&bv.y);

            acc += a0.x * b0.x;
            acc += a0.y * b0.y;
            acc += a1.x * b1.x;
            acc += a1.y * b1.y;
        }

        // Diagonal term (fp32 std, exact): lane `sub` owns column `sub`
        {
            const int xd = (sub == 0) ? xi.x : (sub == 1) ? xi.y : (sub == 2) ? xi.z : xi.w;
            const int yd = (sub == 0) ? yi.x : (sub == 1) ? yi.y : (sub == 2) ? yi.z : yi.w;
            if (xd == yd) {
                const float s = stdv[sub * NB_CAT + xd];
                acc += s * s;
            }
        }

        // Reduce over the 4 chunk lanes
        acc += __shfl_xor_sync(0xffffffffu, acc, 1);
        acc += __shfl_xor_sync(0xffffffffu, acc, 2);

        if (sub == 0) {
            out[p] = acc;
        }
    }
}

extern "C" void kernel_launch(void* const* d_in, const int* in_sizes, int n_in,
                              void* d_out, int out_size)
{
    const int*   x    = (const int*)d_in[0];
    const int*   y    = (const int*)d_in[1];
    const float* cf   = (const float*)d_in[2];
    const float* stdv = (const float*)d_in[3];
    float*       out  = (float*)d_out;

    const int n_pairs = out_size;  // 1048576

    // 1) Convert covar_factor fp32 -> fp16 (same-stream ordering before main)
    {
        const int n = N_COLS * NB_CAT * RANK / 2;
        convert_cf_kernel<<<(n + 255) / 256, 256>>>(cf);
    }

    // 2) Main gather kernel: single resident wave, 8 blocks/SM
    {
        const int threads = 256;
        const int blocks  = 148 * 8;
        pair_cov_kernel<<<blocks, threads>>>(x, y, stdv, out, n_pairs);
    }
}